// round 15
// baseline (speedup 1.0000x reference)
#include <cuda_runtime.h>
#include <cuda_bf16.h>
#include <cstdint>

// Problem constants
#define BATCH 1024
#define HID   512
#define TSZ   24
#define PLEN  256
#define XP0   32          // padded layer0 input width (24 -> 32)
#define NCTA  256         // persistent grid (2 CTAs/SM co-resident)
#define NTHR  512         // 16 warps per CTA

// GRU layer tile config: CTA-tile = 64 rows x 32 gate-cols, 16 warps
#define TM 64
#define TN 32
#define KT 32             // k per tile
#define AST 40            // smem row stride (bf16 elems): 32 + 8 pad

// dynamic smem layout (bytes)
#define G_APART (64 * AST * 2)            // 5120
#define G_WPART (96 * AST * 2)            // 7680
#define G_STAGE (2*G_APART + 2*G_WPART)   // 25600
#define G_SMEM  (4*G_STAGE)               // 102400
#define WPLANE  (32 * AST * 2)            // 2560: one plane within W part

// ---------------------------------------------------------------------------
// Device state (no allocation allowed -> __device__ globals)
// ---------------------------------------------------------------------------
__device__ float         g_h0f[2][BATCH * HID];
__device__ float         g_h1f[2][BATCH * HID];
__device__ __nv_bfloat16 g_h0h[2][BATCH * HID], g_h0l[2][BATCH * HID];
__device__ __nv_bfloat16 g_h1h[2][BATCH * HID], g_h1l[2][BATCH * HID];
__device__ __nv_bfloat16 g_valh[2][BATCH * XP0], g_vall[2][BATCH * XP0];
__device__ __nv_bfloat16 g_w0xh[3 * HID * XP0], g_w0xl[3 * HID * XP0];
__device__ __nv_bfloat16 g_w0hh[3 * HID * HID], g_w0hl[3 * HID * HID];
__device__ __nv_bfloat16 g_w1xh[3 * HID * HID], g_w1xl[3 * HID * HID];
__device__ __nv_bfloat16 g_w1hh[3 * HID * HID], g_w1hl[3 * HID * HID];
// per-row-block arrival counters, padded to separate 32B sectors
__device__ unsigned      g_cA[16 * 8], g_cB[16 * 8], g_cC[16 * 8];

// ---------------------------------------------------------------------------
// helpers
// ---------------------------------------------------------------------------
__device__ __forceinline__ float sigf(float x) { return 1.0f / (1.0f + __expf(-x)); }
__device__ __forceinline__ float tanhf_fast(float x) {
    return 1.0f - 2.0f / (__expf(2.0f * x) + 1.0f);
}

__device__ __forceinline__ uint32_t smem_u32(const void* p) {
    uint32_t a;
    asm("{ .reg .u64 t; cvta.to.shared.u64 t, %1; cvt.u32.u64 %0, t; }" : "=r"(a) : "l"(p));
    return a;
}

__device__ __forceinline__ void cpa16(uint32_t dst, const void* src) {
    asm volatile("cp.async.cg.shared.global [%0], [%1], 16;" :: "r"(dst), "l"(src) : "memory");
}
__device__ __forceinline__ void cpa_commit() {
    asm volatile("cp.async.commit_group;" ::: "memory");
}
template<int N>
__device__ __forceinline__ void cpa_wait() {
    asm volatile("cp.async.wait_group %0;" :: "n"(N) : "memory");
}

__device__ __forceinline__ void ldsm4(uint32_t* r, uint32_t addr) {
    asm volatile("ldmatrix.sync.aligned.m8n8.x4.shared.b16 {%0,%1,%2,%3}, [%4];"
                 : "=r"(r[0]), "=r"(r[1]), "=r"(r[2]), "=r"(r[3]) : "r"(addr));
}
__device__ __forceinline__ void ldsm2(uint32_t* r, uint32_t addr) {
    asm volatile("ldmatrix.sync.aligned.m8n8.x2.shared.b16 {%0,%1}, [%2];"
                 : "=r"(r[0]), "=r"(r[1]) : "r"(addr));
}

__device__ __forceinline__ void mma_bf16(float* c, const uint32_t* a,
                                         uint32_t b0, uint32_t b1) {
    asm volatile(
        "mma.sync.aligned.m16n8k16.row.col.f32.bf16.bf16.f32 "
        "{%0,%1,%2,%3}, {%4,%5,%6,%7}, {%8,%9}, {%0,%1,%2,%3};"
        : "+f"(c[0]), "+f"(c[1]), "+f"(c[2]), "+f"(c[3])
        : "r"(a[0]), "r"(a[1]), "r"(a[2]), "r"(a[3]), "r"(b0), "r"(b1));
}

__device__ __forceinline__ void split_bf16(float x, __nv_bfloat16& h, __nv_bfloat16& l) {
    h = __float2bfloat16(x);
    l = __float2bfloat16(x - __bfloat162float(h));
}

__device__ __forceinline__ unsigned ld_acq(const unsigned* p) {
    unsigned v;
    asm volatile("ld.acquire.gpu.global.u32 %0, [%1];" : "=r"(v) : "l"(p));
    return v;
}
__device__ __forceinline__ void spin_until(const unsigned* c, unsigned tgt) {
    unsigned v = ld_acq(c);
    while (v < tgt) { __nanosleep(32); v = ld_acq(c); }
}

// ---------------------------------------------------------------------------
// GRU layer step: CTA = 64 rows x 32 cols, 16 warps; warp = 16 rows x 8 cols.
// Tile order: h-phase tiles FIRST, x-phase tiles LAST (x staging waits xcnt).
// ---------------------------------------------------------------------------
template<int LAYER>
__device__ __forceinline__ void gru_layer_step(char* sm, int cur,
                                               const float* __restrict__ bih,
                                               const float* __restrict__ bhh,
                                               const unsigned* xcnt, unsigned xtgt)
{
    constexpr int KPH0 = (LAYER == 0) ? XP0 : HID;  // x-phase K
    constexpr int NTH  = HID / KT;                  // 16 h-tiles
    constexpr int NT   = NTH + KPH0 / KT;           // 17 or 32
    const int nxt = cur ^ 1;

    const __nv_bfloat16* __restrict__ xh = (LAYER == 0) ? g_valh[cur] : g_h0h[nxt];
    const __nv_bfloat16* __restrict__ xl = (LAYER == 0) ? g_vall[cur] : g_h0l[nxt];
    const __nv_bfloat16* __restrict__ hh = (LAYER == 0) ? g_h0h[cur] : g_h1h[cur];
    const __nv_bfloat16* __restrict__ hl = (LAYER == 0) ? g_h0l[cur] : g_h1l[cur];
    const float* __restrict__ hinf       = (LAYER == 0) ? g_h0f[cur] : g_h1f[cur];
    float* __restrict__ houtf            = (LAYER == 0) ? g_h0f[nxt] : g_h1f[nxt];
    __nv_bfloat16* __restrict__ houth    = (LAYER == 0) ? g_h0h[nxt] : g_h1h[nxt];
    __nv_bfloat16* __restrict__ houtl    = (LAYER == 0) ? g_h0l[nxt] : g_h1l[nxt];
    const __nv_bfloat16* __restrict__ Wxh  = (LAYER == 0) ? g_w0xh : g_w1xh;
    const __nv_bfloat16* __restrict__ Wxl  = (LAYER == 0) ? g_w0xl : g_w1xl;
    const __nv_bfloat16* __restrict__ Whhh = (LAYER == 0) ? g_w0hh : g_w1hh;
    const __nv_bfloat16* __restrict__ Whhl = (LAYER == 0) ? g_w0hl : g_w1hl;

    const int tid  = threadIdx.x;
    const int w    = tid >> 5;
    const int l    = tid & 31;
    const int rg   = w & 3;           // row group: rows rg*16..rg*16+15
    const int cq   = w >> 2;          // col quarter: cols cq*8..cq*8+7
    const int rowBase = (blockIdx.x & 15) * TM;
    const int colBase = (blockIdx.x >> 4) * TN;
    const uint32_t smb = smem_u32(sm);

    // accumulators: [plane r,z,inn,hn][reg(4)] = 16 regs
    float cAcc[4][4];
    {
        const int c4 = l & 3;
        const int j0 = colBase + cq * 8 + 2 * c4;
        const float br0 = __ldg(bih + j0)     + __ldg(bhh + j0);
        const float br1 = __ldg(bih + j0 + 1) + __ldg(bhh + j0 + 1);
        const float bz0 = __ldg(bih + HID + j0)     + __ldg(bhh + HID + j0);
        const float bz1 = __ldg(bih + HID + j0 + 1) + __ldg(bhh + HID + j0 + 1);
        const float bi0 = __ldg(bih + 2 * HID + j0);
        const float bi1 = __ldg(bih + 2 * HID + j0 + 1);
        const float bn0 = __ldg(bhh + 2 * HID + j0);
        const float bn1 = __ldg(bhh + 2 * HID + j0 + 1);
        cAcc[0][0] = br0; cAcc[0][1] = br1; cAcc[0][2] = br0; cAcc[0][3] = br1;
        cAcc[1][0] = bz0; cAcc[1][1] = bz1; cAcc[1][2] = bz0; cAcc[1][3] = bz1;
        cAcc[2][0] = bi0; cAcc[2][1] = bi1; cAcc[2][2] = bi0; cAcc[2][3] = bi1;
        cAcc[3][0] = bn0; cAcc[3][1] = bn1; cAcc[3][2] = bn0; cAcc[3][3] = bn1;
    }

    // ---- A loader: 512 chunks (hi 256 + lo 256), 1 per thread ----
    const int aPart = tid >> 8;             // 0 = hi, 1 = lo
    const int aIdx  = tid & 255;
    const int aRow  = rowBase + (aIdx >> 2);
    const int aCol  = (aIdx & 3) << 3;
    const uint32_t aDst = (uint32_t)(aPart * G_APART + (((aIdx >> 2) * AST + aCol) << 1));
    const __nv_bfloat16* aBaseH = (aPart ? hl : hh) + (size_t)aRow * HID  + aCol;
    const __nv_bfloat16* aBaseX = (aPart ? xl : xh) + (size_t)aRow * KPH0 + aCol;

    // ---- W loader: 768 chunks; chunk1 for all threads, chunk2 for tid<256 ----
    const int p1   = (tid >= 384) ? 1 : 0;
    const int idx1 = tid - p1 * 384;        // 0..383
    const int rr1  = idx1 >> 2;             // 0..95
    const int cc1  = (idx1 & 3) << 3;
    const int gr1  = (rr1 >> 5) * HID + colBase + (rr1 & 31);
    const uint32_t wDst1 = (uint32_t)(2 * G_APART + p1 * G_WPART + ((rr1 * AST + cc1) << 1));
    const __nv_bfloat16* w1H = (p1 ? Whhl : Whhh) + (size_t)gr1 * HID  + cc1;
    const __nv_bfloat16* w1X = (p1 ? Wxl  : Wxh ) + (size_t)gr1 * KPH0 + cc1;

    const int idx2 = (tid & 255) + 128;     // 128..383 (valid when tid<256)
    const int rr2  = idx2 >> 2;
    const int cc2  = (idx2 & 3) << 3;
    const int gr2  = (rr2 >> 5) * HID + colBase + (rr2 & 31);
    const uint32_t wDst2 = (uint32_t)(2 * G_APART + G_WPART + ((rr2 * AST + cc2) << 1));
    const __nv_bfloat16* w2H = Whhl + (size_t)gr2 * HID  + cc2;
    const __nv_bfloat16* w2X = Wxl  + (size_t)gr2 * KPH0 + cc2;

    // ---- ldmatrix byte offsets ----
    const uint32_t aOffB =
        (uint32_t)(((rg * 16 + (l & 7) + (((l >> 3) & 1) << 3)) * AST + ((l >> 4) << 3)) << 1);
    const uint32_t wOffB =
        (uint32_t)(((cq * 8 + (l & 7)) * AST + (((l >> 3) & 1) << 3)) << 1);

    auto stageT = [&](int t) {
        const int buf = t & 3;
        const bool hph = (t < NTH);
        const int koff = (hph ? t : t - NTH) * KT;
        const uint32_t stg = smb + buf * G_STAGE;
        cpa16(stg + aDst, (hph ? aBaseH : aBaseX) + koff);
        cpa16(stg + wDst1, (hph ? w1H : w1X) + koff);
        if (tid < 256) cpa16(stg + wDst2, (hph ? w2H : w2X) + koff);
    };

    auto computeT = [&](int t) {
        const int buf = t & 3;
        const bool hph = (t < NTH);
        const uint32_t stg = smb + buf * G_STAGE;
        const uint32_t aHp = stg + aOffB;
        const uint32_t aLp = stg + G_APART + aOffB;
        const uint32_t wHp = stg + 2 * G_APART + wOffB;
        const uint32_t wLp = stg + 2 * G_APART + G_WPART + wOffB;
        #pragma unroll
        for (int kc = 0; kc < 2; kc++) {
            uint32_t ah[4], al[4];
            ldsm4(ah, aHp + kc * 32);
            ldsm4(al, aLp + kc * 32);
            #pragma unroll
            for (int p = 0; p < 3; p++) {
                uint32_t bh[2], bl[2];
                ldsm2(bh, wHp + p * WPLANE + kc * 32);
                ldsm2(bl, wLp + p * WPLANE + kc * 32);
                float* C = (p == 2) ? (hph ? cAcc[3] : cAcc[2]) : cAcc[p];
                mma_bf16(C, ah, bh[0], bh[1]);
                mma_bf16(C, al, bh[0], bh[1]);
                mma_bf16(C, ah, bl[0], bl[1]);
            }
        }
    };

    stageT(0); cpa_commit();
    stageT(1); cpa_commit();
    stageT(2); cpa_commit();
    for (int t = 0; t < NT; t++) {
        cpa_wait<2>();
        if (t + 3 == NTH && tid == 0) spin_until(xcnt, xtgt);
        __syncthreads();
        computeT(t);
        if (t + 3 < NT) stageT(t + 3);
        cpa_commit();
    }

    // GRU epilogue
    const int g  = l >> 2;
    const int c4 = l & 3;
    const int R0 = rowBase + rg * 16 + g;
    const int R1 = R0 + 8;
    const int j0 = colBase + cq * 8 + 2 * c4;
    {
        const float2 h0v = __ldcg((const float2*)(hinf + (size_t)R0 * HID + j0));
        const float2 h1v = __ldcg((const float2*)(hinf + (size_t)R1 * HID + j0));
        float o[4];
        const float hvv[4] = { h0v.x, h0v.y, h1v.x, h1v.y };
        #pragma unroll
        for (int i = 0; i < 4; i++) {
            const float r_ = sigf(cAcc[0][i]);
            const float z_ = sigf(cAcc[1][i]);
            const float n_ = tanhf_fast(cAcc[2][i] + r_ * cAcc[3][i]);
            o[i] = (1.0f - z_) * n_ + z_ * hvv[i];
        }
        *(float2*)&houtf[(size_t)R0 * HID + j0] = make_float2(o[0], o[1]);
        *(float2*)&houtf[(size_t)R1 * HID + j0] = make_float2(o[2], o[3]);
        __nv_bfloat16 h0a, l0a, h0b, l0b, h1a, l1a, h1b, l1b;
        split_bf16(o[0], h0a, l0a); split_bf16(o[1], h0b, l0b);
        split_bf16(o[2], h1a, l1a); split_bf16(o[3], h1b, l1b);
        *(__nv_bfloat162*)&houth[(size_t)R0 * HID + j0] = __halves2bfloat162(h0a, h0b);
        *(__nv_bfloat162*)&houtl[(size_t)R0 * HID + j0] = __halves2bfloat162(l0a, l0b);
        *(__nv_bfloat162*)&houth[(size_t)R1 * HID + j0] = __halves2bfloat162(h1a, h1b);
        *(__nv_bfloat162*)&houtl[(size_t)R1 * HID + j0] = __halves2bfloat162(l1a, l1b);
    }
}

// ---------------------------------------------------------------------------
// Output head: warp-per-row on CTAs 0..63 (16 warps x 64 = 1024 rows).
// ---------------------------------------------------------------------------
__device__ __forceinline__ void head_step(int cur,
                                          const float* __restrict__ Wout,
                                          const float* __restrict__ bout,
                                          float* __restrict__ outputs, int step)
{
    const int nxt  = cur ^ 1;
    const int w    = threadIdx.x >> 5;
    const int lane = threadIdx.x & 31;
    const int row  = blockIdx.x * 16 + w;
    const float* __restrict__ h1 = g_h1f[nxt];

    float xv[16];
    {
        const float4* hr = (const float4*)(h1 + (size_t)row * HID);
        #pragma unroll
        for (int q = 0; q < 4; q++) {
            float4 v = __ldcg(&hr[lane * 4 + q]);
            xv[q * 4 + 0] = fmaxf(v.x, 0.f);
            xv[q * 4 + 1] = fmaxf(v.y, 0.f);
            xv[q * 4 + 2] = fmaxf(v.z, 0.f);
            xv[q * 4 + 3] = fmaxf(v.w, 0.f);
        }
    }

    float s[TSZ];
    #pragma unroll
    for (int j = 0; j < TSZ; j++) {
        const float4* wr = (const float4*)(Wout + (size_t)j * HID + lane * 16);
        float a = 0.f;
        #pragma unroll
        for (int q = 0; q < 4; q++) {
            const float4 wv = __ldg(&wr[q]);
            a = fmaf(xv[q * 4 + 0], wv.x, a);
            a = fmaf(xv[q * 4 + 1], wv.y, a);
            a = fmaf(xv[q * 4 + 2], wv.z, a);
            a = fmaf(xv[q * 4 + 3], wv.w, a);
        }
        s[j] = a;
    }

    #pragma unroll
    for (int off = 16; off >= 1; off >>= 1) {
        #pragma unroll
        for (int j = 0; j < TSZ; j++)
            s[j] += __shfl_xor_sync(0xFFFFFFFFu, s[j], off);
    }

    if (lane < TSZ) {
        const float v = sigf(s[lane] + __ldg(bout + lane));
        outputs[(size_t)row * (PLEN * TSZ) + (size_t)step * TSZ + lane] = v;
        __nv_bfloat16 vh, vl;
        split_bf16(v, vh, vl);
        g_valh[nxt][row * XP0 + lane] = vh;
        g_vall[nxt][row * XP0 + lane] = vl;
    }
}

// ---------------------------------------------------------------------------
// Persistent whole-rollout kernel: per-row-block flag sync.
// Head: 64 CTAs x 16 rows => 4 head-CTAs per 64-row block (cC +4 per step).
// ---------------------------------------------------------------------------
__global__ __launch_bounds__(NTHR, 2)
void decoder_persistent(const float* __restrict__ bih0, const float* __restrict__ bhh0,
                        const float* __restrict__ bih1, const float* __restrict__ bhh1,
                        const float* __restrict__ Wout, const float* __restrict__ bout,
                        float* __restrict__ out)
{
    extern __shared__ __align__(16) char sm[];
    const int tid = threadIdx.x;
    const int rb  = blockIdx.x & 15;          // row-block of this layer-CTA
    const int hrb = (blockIdx.x >> 2) & 15;   // row-block of this head-CTA (bid<64)
    unsigned* cA = &g_cA[rb * 8];
    unsigned* cB = &g_cB[rb * 8];
    unsigned* cC = &g_cC[rb * 8];
    unsigned* cBh = &g_cB[hrb * 8];
    unsigned* cCh = &g_cC[hrb * 8];

    auto arrive = [&](unsigned* c) {
        __threadfence();
        __syncthreads();
        if (tid == 0) atomicAdd(c, 1u);
    };

    for (int s = 0; s < PLEN; s++) {
        const int cur = s & 1;

        // ---- Layer 0: entry = rb's L0(s-1) done; x-tile waits head(s-1) of rb.
        if (tid == 0) spin_until(cA, 16u * (unsigned)s);
        __syncthreads();
        gru_layer_step<0>(sm, cur, bih0, bhh0, cC, 4u * (unsigned)s);
        arrive(cA);

        // ---- Layer 1: entry = rb's L1(s-1); WAR vs head(s-2); x waits L0(s).
        if (tid == 0) {
            spin_until(cB, 16u * (unsigned)s);
            if (s >= 2) spin_until(cC, 4u * (unsigned)(s - 1));
        }
        __syncthreads();
        gru_layer_step<1>(sm, cur, bih1, bhh1, cA, 16u * (unsigned)(s + 1));
        arrive(cB);

        // ---- Head on CTAs 0..63 (16 rows each): needs rb=bid>>2's L1(s).
        if (blockIdx.x < BATCH / 16) {
            if (tid == 0) spin_until(cBh, 16u * (unsigned)(s + 1));
            __syncthreads();
            head_step(cur, Wout, bout, out, s);
            __threadfence();
            __syncthreads();
            if (tid == 0) atomicAdd(cCh, 1u);
        }
    }

    // final hidden copy
    if (tid < 16) {
        spin_until(&g_cA[tid * 8], 16u * (unsigned)PLEN);
        spin_until(&g_cB[tid * 8], 16u * (unsigned)PLEN);
    }
    __syncthreads();
    constexpr int CH = BATCH * HID / NCTA;   // 2048
    const int base = blockIdx.x * CH;
    float* dst = out + (size_t)BATCH * PLEN * TSZ;
    for (int i = tid; i < CH; i += blockDim.x) {
        dst[base + i]               = __ldcg(&g_h0f[0][base + i]);
        dst[BATCH * HID + base + i] = __ldcg(&g_h1f[0][base + i]);
    }
}

// ---------------------------------------------------------------------------
// init: reset flags, copy/split initial hidden, zero val, split weights
// ---------------------------------------------------------------------------
__global__ void init_kernel(const float* __restrict__ hidden,
                            const float* __restrict__ Wih0,
                            const float* __restrict__ Whh0,
                            const float* __restrict__ Wih1,
                            const float* __restrict__ Whh1)
{
    const int i = blockIdx.x * blockDim.x + threadIdx.x;
    const __nv_bfloat16 z16 = __float2bfloat16(0.0f);

    if (i < 16 * 8) { g_cA[i] = 0; g_cB[i] = 0; g_cC[i] = 0; }

    if (i < BATCH * HID) {
        const float a = hidden[i];
        const float b = hidden[BATCH * HID + i];
        g_h0f[0][i] = a;
        g_h1f[0][i] = b;
        split_bf16(a, g_h0h[0][i], g_h0l[0][i]);
        split_bf16(b, g_h1h[0][i], g_h1l[0][i]);
    }
    if (i < 2 * BATCH * XP0) {
        (&g_valh[0][0])[i] = z16;
        (&g_vall[0][0])[i] = z16;
    }
    if (i < 3 * HID * XP0) {
        const int r = i / XP0;
        const int k = i % XP0;
        const float ww = (k < TSZ) ? Wih0[r * TSZ + k] : 0.0f;
        split_bf16(ww, g_w0xh[i], g_w0xl[i]);
    }
    if (i < 3 * HID * HID) {
        split_bf16(Whh0[i], g_w0hh[i], g_w0hl[i]);
        split_bf16(Wih1[i], g_w1xh[i], g_w1xl[i]);
        split_bf16(Whh1[i], g_w1hh[i], g_w1hl[i]);
    }
}

// ---------------------------------------------------------------------------
// host
// ---------------------------------------------------------------------------
extern "C" void kernel_launch(void* const* d_in, const int* in_sizes, int n_in,
                              void* d_out, int out_size)
{
    const float* hidden = (const float*)d_in[0];
    const float* Wih0   = (const float*)d_in[1];
    const float* Whh0   = (const float*)d_in[2];
    const float* bih0   = (const float*)d_in[3];
    const float* bhh0   = (const float*)d_in[4];
    const float* Wih1   = (const float*)d_in[5];
    const float* Whh1   = (const float*)d_in[6];
    const float* bih1   = (const float*)d_in[7];
    const float* bhh1   = (const float*)d_in[8];
    const float* Wout   = (const float*)d_in[9];
    const float* bout   = (const float*)d_in[10];
    float* out = (float*)d_out;

    cudaFuncSetAttribute(decoder_persistent,
                         cudaFuncAttributeMaxDynamicSharedMemorySize, G_SMEM);

    init_kernel<<<(3 * HID * HID + 255) / 256, 256>>>(hidden, Wih0, Whh0, Wih1, Whh1);
    decoder_persistent<<<NCTA, NTHR, G_SMEM>>>(bih0, bhh0, bih1, bhh1, Wout, bout, out);
}

// round 16
// speedup vs baseline: 1.6438x; 1.6438x over previous
#include <cuda_runtime.h>
#include <cuda_fp16.h>
#include <cstdint>

// Problem constants
#define BATCH 1024
#define HID   512
#define TSZ   24
#define PLEN  256
#define XP0   32          // padded layer0 input width (24 -> 32)
#define NCTA  256         // persistent grid (2 CTAs/SM co-resident)

// GRU layer tile config: CTA-tile = 64 rows x 32 gate-cols, 8 warps
#define TM 64
#define TN 32
#define KT 32             // k per tile
#define AST 40            // smem row stride (fp16 elems): 32 + 8 pad

// dynamic smem layout (bytes): A hi | A lo | W hi
#define G_APART (64 * AST * 2)            // 5120
#define G_WPART (96 * AST * 2)            // 7680
#define G_STAGE (2*G_APART + G_WPART)     // 17920
#define G_SMEM  (4*G_STAGE)               // 71680
#define WPLANE  (32 * AST * 2)            // 2560: one plane within W part

// ---------------------------------------------------------------------------
// Device state (no allocation allowed -> __device__ globals)
// ---------------------------------------------------------------------------
__device__ float  g_h0f[2][BATCH * HID];
__device__ float  g_h1f[2][BATCH * HID];
__device__ __half g_h0h[2][BATCH * HID], g_h0l[2][BATCH * HID];
__device__ __half g_h1h[2][BATCH * HID], g_h1l[2][BATCH * HID];
__device__ __half g_valh[2][BATCH * XP0], g_vall[2][BATCH * XP0];
__device__ __half g_w0x[3 * HID * XP0];
__device__ __half g_w0h[3 * HID * HID];
__device__ __half g_w1x[3 * HID * HID];
__device__ __half g_w1h[3 * HID * HID];
// per-row-block arrival counters, padded to separate 32B sectors
__device__ unsigned g_cA[16 * 8], g_cB[16 * 8], g_cC[16 * 8];

// ---------------------------------------------------------------------------
// helpers
// ---------------------------------------------------------------------------
__device__ __forceinline__ float sigf(float x) { return 1.0f / (1.0f + __expf(-x)); }
__device__ __forceinline__ float tanhf_fast(float x) {
    return 1.0f - 2.0f / (__expf(2.0f * x) + 1.0f);
}

__device__ __forceinline__ uint32_t smem_u32(const void* p) {
    uint32_t a;
    asm("{ .reg .u64 t; cvta.to.shared.u64 t, %1; cvt.u32.u64 %0, t; }" : "=r"(a) : "l"(p));
    return a;
}

__device__ __forceinline__ void cpa16(uint32_t dst, const void* src) {
    asm volatile("cp.async.cg.shared.global [%0], [%1], 16;" :: "r"(dst), "l"(src) : "memory");
}
__device__ __forceinline__ void cpa_commit() {
    asm volatile("cp.async.commit_group;" ::: "memory");
}
template<int N>
__device__ __forceinline__ void cpa_wait() {
    asm volatile("cp.async.wait_group %0;" :: "n"(N) : "memory");
}

__device__ __forceinline__ void ldsm4(uint32_t* r, uint32_t addr) {
    asm volatile("ldmatrix.sync.aligned.m8n8.x4.shared.b16 {%0,%1,%2,%3}, [%4];"
                 : "=r"(r[0]), "=r"(r[1]), "=r"(r[2]), "=r"(r[3]) : "r"(addr));
}

__device__ __forceinline__ void mma_fp16(float* c, const uint32_t* a,
                                         uint32_t b0, uint32_t b1) {
    asm volatile(
        "mma.sync.aligned.m16n8k16.row.col.f32.f16.f16.f32 "
        "{%0,%1,%2,%3}, {%4,%5,%6,%7}, {%8,%9}, {%0,%1,%2,%3};"
        : "+f"(c[0]), "+f"(c[1]), "+f"(c[2]), "+f"(c[3])
        : "r"(a[0]), "r"(a[1]), "r"(a[2]), "r"(a[3]), "r"(b0), "r"(b1));
}

__device__ __forceinline__ void split_fp16(float x, __half& h, __half& l) {
    h = __float2half_rn(x);
    l = __float2half_rn(x - __half2float(h));
}

__device__ __forceinline__ unsigned ld_acq(const unsigned* p) {
    unsigned v;
    asm volatile("ld.acquire.gpu.global.u32 %0, [%1];" : "=r"(v) : "l"(p));
    return v;
}
__device__ __forceinline__ void spin_until(const unsigned* c, unsigned tgt) {
    unsigned v = ld_acq(c);
    while (v < tgt) { __nanosleep(32); v = ld_acq(c); }
}

// ---------------------------------------------------------------------------
// GRU layer step: CTA = 64 rows x 32 cols; warp = 16 rows x 16 cols.
// fp16 2-term split: Ah*Wh + Al*Wh (weights = fp16-rounded, A error corrected).
// Tile order: h-phase tiles FIRST, x-phase tiles LAST (x staging waits xcnt).
// ---------------------------------------------------------------------------
template<int LAYER>
__device__ __forceinline__ void gru_layer_step(char* sm, int cur,
                                               const float* __restrict__ bih,
                                               const float* __restrict__ bhh,
                                               const unsigned* xcnt, unsigned xtgt)
{
    constexpr int KPH0 = (LAYER == 0) ? XP0 : HID;  // x-phase K
    constexpr int NTH  = HID / KT;                  // 16 h-tiles
    constexpr int NT   = NTH + KPH0 / KT;           // 17 or 32
    const int nxt = cur ^ 1;

    const __half* __restrict__ xh = (LAYER == 0) ? g_valh[cur] : g_h0h[nxt];
    const __half* __restrict__ xl = (LAYER == 0) ? g_vall[cur] : g_h0l[nxt];
    const __half* __restrict__ hh = (LAYER == 0) ? g_h0h[cur] : g_h1h[cur];
    const __half* __restrict__ hl = (LAYER == 0) ? g_h0l[cur] : g_h1l[cur];
    const float* __restrict__ hinf = (LAYER == 0) ? g_h0f[cur] : g_h1f[cur];
    float* __restrict__ houtf      = (LAYER == 0) ? g_h0f[nxt] : g_h1f[nxt];
    __half* __restrict__ houth     = (LAYER == 0) ? g_h0h[nxt] : g_h1h[nxt];
    __half* __restrict__ houtl     = (LAYER == 0) ? g_h0l[nxt] : g_h1l[nxt];
    const __half* __restrict__ Wx  = (LAYER == 0) ? g_w0x : g_w1x;
    const __half* __restrict__ Wh  = (LAYER == 0) ? g_w0h : g_w1h;

    const int tid  = threadIdx.x;
    const int w    = tid >> 5;
    const int l    = tid & 31;
    const int rg   = w & 3;
    const int ch   = w >> 2;
    const int rowBase = (blockIdx.x & 15) * TM;
    const int colBase = (blockIdx.x >> 4) * TN;
    const uint32_t smb = smem_u32(sm);

    // accumulators: [plane r,z,inn,hn][nf(2)][reg(4)] = 32 regs
    float cAcc[4][2][4];
    {
        const int c4 = l & 3;
        #pragma unroll
        for (int nf = 0; nf < 2; nf++) {
            const int j0 = colBase + ch * 16 + nf * 8 + 2 * c4;
            const float br0 = __ldg(bih + j0)     + __ldg(bhh + j0);
            const float br1 = __ldg(bih + j0 + 1) + __ldg(bhh + j0 + 1);
            const float bz0 = __ldg(bih + HID + j0)     + __ldg(bhh + HID + j0);
            const float bz1 = __ldg(bih + HID + j0 + 1) + __ldg(bhh + HID + j0 + 1);
            const float bi0 = __ldg(bih + 2 * HID + j0);
            const float bi1 = __ldg(bih + 2 * HID + j0 + 1);
            const float bn0 = __ldg(bhh + 2 * HID + j0);
            const float bn1 = __ldg(bhh + 2 * HID + j0 + 1);
            cAcc[0][nf][0] = br0; cAcc[0][nf][1] = br1; cAcc[0][nf][2] = br0; cAcc[0][nf][3] = br1;
            cAcc[1][nf][0] = bz0; cAcc[1][nf][1] = bz1; cAcc[1][nf][2] = bz0; cAcc[1][nf][3] = bz1;
            cAcc[2][nf][0] = bi0; cAcc[2][nf][1] = bi1; cAcc[2][nf][2] = bi0; cAcc[2][nf][3] = bi1;
            cAcc[3][nf][0] = bn0; cAcc[3][nf][1] = bn1; cAcc[3][nf][2] = bn0; cAcc[3][nf][3] = bn1;
        }
    }

    // ---- A loader: 256 (row,kc) chunks over 256 threads; hi and lo each ----
    const int aRow   = rowBase + (tid >> 2);
    const int akcOff = (tid & 3) << 3;
    const uint32_t aDst = (uint32_t)(((tid >> 2) * AST + ((tid & 3) << 3)) << 1);
    const __half* aBaseHh = hh + (size_t)aRow * HID  + akcOff;
    const __half* aBaseHl = hl + (size_t)aRow * HID  + akcOff;
    const __half* aBaseXh = xh + (size_t)aRow * KPH0 + akcOff;
    const __half* aBaseXl = xl + (size_t)aRow * KPH0 + akcOff;

    // ---- W loader (hi only): 384 chunks; chunk1 = tid, chunk2 = tid+256 (tid<128)
    const int rr1 = tid >> 2;                    // rows 0..63 (planes 0..1)
    const int cc1 = (tid & 3) << 3;
    const int gr1 = (rr1 >> 5) * HID + colBase + (rr1 & 31);
    const uint32_t wDst1 = (uint32_t)(2 * G_APART + ((rr1 * AST + cc1) << 1));
    const __half* w1H = Wh + (size_t)gr1 * HID  + cc1;
    const __half* w1X = Wx + (size_t)gr1 * KPH0 + cc1;

    const int rr2 = 64 + (tid >> 2);             // rows 64..95 (plane 2), tid<128
    const int cc2 = (tid & 3) << 3;
    const int gr2 = 2 * HID + colBase + (rr2 & 31);
    const uint32_t wDst2 = (uint32_t)(2 * G_APART + ((rr2 * AST + cc2) << 1));
    const __half* w2H = Wh + (size_t)gr2 * HID  + cc2;
    const __half* w2X = Wx + (size_t)gr2 * KPH0 + cc2;

    // ---- ldmatrix byte offsets ----
    const uint32_t aOffB =
        (uint32_t)(((rg * 16 + (l & 7) + (((l >> 3) & 1) << 3)) * AST + ((l >> 4) << 3)) << 1);
    const uint32_t wOffB =
        (uint32_t)(((ch * 16 + (l & 7) + (((l >> 4) & 1) << 3)) * AST + (((l >> 3) & 1) << 3)) << 1);

    auto stageT = [&](int t) {
        const int buf = t & 3;
        const bool hph = (t < NTH);
        const int koff = (hph ? t : t - NTH) * KT;
        const uint32_t stg = smb + buf * G_STAGE;
        cpa16(stg + aDst,           (hph ? aBaseHh : aBaseXh) + koff);
        cpa16(stg + G_APART + aDst, (hph ? aBaseHl : aBaseXl) + koff);
        cpa16(stg + wDst1, (hph ? w1H : w1X) + koff);
        if (tid < 128) cpa16(stg + wDst2, (hph ? w2H : w2X) + koff);
    };

    auto computeT = [&](int t) {
        const int buf = t & 3;
        const bool hph = (t < NTH);
        const uint32_t stg = smb + buf * G_STAGE;
        const uint32_t aHp = stg + aOffB;
        const uint32_t aLp = stg + G_APART + aOffB;
        const uint32_t wHp = stg + 2 * G_APART + wOffB;
        #pragma unroll
        for (int kc = 0; kc < 2; kc++) {
            uint32_t ah[4], al[4];
            ldsm4(ah, aHp + kc * 32);
            ldsm4(al, aLp + kc * 32);
            #pragma unroll
            for (int p = 0; p < 3; p++) {
                uint32_t bh[4];
                ldsm4(bh, wHp + p * WPLANE + kc * 32);
                float (*C)[4] = (p == 2) ? (hph ? cAcc[3] : cAcc[2]) : cAcc[p];
                #pragma unroll
                for (int nf = 0; nf < 2; nf++) {
                    mma_fp16(C[nf], ah, bh[2 * nf], bh[2 * nf + 1]);
                    mma_fp16(C[nf], al, bh[2 * nf], bh[2 * nf + 1]);
                }
            }
        }
    };

    stageT(0); cpa_commit();
    stageT(1); cpa_commit();
    stageT(2); cpa_commit();
    for (int t = 0; t < NT; t++) {
        cpa_wait<2>();
        if (t + 3 == NTH && tid == 0) spin_until(xcnt, xtgt);
        __syncthreads();
        computeT(t);
        if (t + 3 < NT) stageT(t + 3);
        cpa_commit();
    }

    // GRU epilogue (hinf via __ldcg: L2-coherent cross-CTA reads)
    const int g  = l >> 2;
    const int c4 = l & 3;
    const int R0 = rowBase + rg * 16 + g;
    const int R1 = R0 + 8;
    #pragma unroll
    for (int nf = 0; nf < 2; nf++) {
        const int j0 = colBase + ch * 16 + nf * 8 + 2 * c4;
        const float2 h0v = __ldcg((const float2*)(hinf + (size_t)R0 * HID + j0));
        const float2 h1v = __ldcg((const float2*)(hinf + (size_t)R1 * HID + j0));
        float o[4];
        const float hvv[4] = { h0v.x, h0v.y, h1v.x, h1v.y };
        #pragma unroll
        for (int i = 0; i < 4; i++) {
            const float r_ = sigf(cAcc[0][nf][i]);
            const float z_ = sigf(cAcc[1][nf][i]);
            const float n_ = tanhf_fast(cAcc[2][nf][i] + r_ * cAcc[3][nf][i]);
            o[i] = (1.0f - z_) * n_ + z_ * hvv[i];
        }
        *(float2*)&houtf[(size_t)R0 * HID + j0] = make_float2(o[0], o[1]);
        *(float2*)&houtf[(size_t)R1 * HID + j0] = make_float2(o[2], o[3]);
        __half h0a, l0a, h0b, l0b, h1a, l1a, h1b, l1b;
        split_fp16(o[0], h0a, l0a); split_fp16(o[1], h0b, l0b);
        split_fp16(o[2], h1a, l1a); split_fp16(o[3], h1b, l1b);
        *(__half2*)&houth[(size_t)R0 * HID + j0] = __halves2half2(h0a, h0b);
        *(__half2*)&houtl[(size_t)R0 * HID + j0] = __halves2half2(l0a, l0b);
        *(__half2*)&houth[(size_t)R1 * HID + j0] = __halves2half2(h1a, h1b);
        *(__half2*)&houtl[(size_t)R1 * HID + j0] = __halves2half2(l1a, l1b);
    }
}

// ---------------------------------------------------------------------------
// Output head: warp-per-row on CTAs 0..127 (1024 rows).
// ---------------------------------------------------------------------------
__device__ __forceinline__ void head_step(int cur,
                                          const float* __restrict__ Wout,
                                          const float* __restrict__ bout,
                                          float* __restrict__ outputs, int step)
{
    const int nxt  = cur ^ 1;
    const int w    = threadIdx.x >> 5;
    const int lane = threadIdx.x & 31;
    const int row  = blockIdx.x * 8 + w;
    const float* __restrict__ h1 = g_h1f[nxt];

    float xv[16];
    {
        const float4* hr = (const float4*)(h1 + (size_t)row * HID);
        #pragma unroll
        for (int q = 0; q < 4; q++) {
            float4 v = __ldcg(&hr[lane * 4 + q]);
            xv[q * 4 + 0] = fmaxf(v.x, 0.f);
            xv[q * 4 + 1] = fmaxf(v.y, 0.f);
            xv[q * 4 + 2] = fmaxf(v.z, 0.f);
            xv[q * 4 + 3] = fmaxf(v.w, 0.f);
        }
    }

    float s[TSZ];
    #pragma unroll
    for (int j = 0; j < TSZ; j++) {
        const float4* wr = (const float4*)(Wout + (size_t)j * HID + lane * 16);
        float a = 0.f;
        #pragma unroll
        for (int q = 0; q < 4; q++) {
            const float4 wv = __ldg(&wr[q]);
            a = fmaf(xv[q * 4 + 0], wv.x, a);
            a = fmaf(xv[q * 4 + 1], wv.y, a);
            a = fmaf(xv[q * 4 + 2], wv.z, a);
            a = fmaf(xv[q * 4 + 3], wv.w, a);
        }
        s[j] = a;
    }

    #pragma unroll
    for (int off = 16; off >= 1; off >>= 1) {
        #pragma unroll
        for (int j = 0; j < TSZ; j++)
            s[j] += __shfl_xor_sync(0xFFFFFFFFu, s[j], off);
    }

    if (lane < TSZ) {
        const float v = sigf(s[lane] + __ldg(bout + lane));
        outputs[(size_t)row * (PLEN * TSZ) + (size_t)step * TSZ + lane] = v;
        __half vh, vl;
        split_fp16(v, vh, vl);
        g_valh[nxt][row * XP0 + lane] = vh;
        g_vall[nxt][row * XP0 + lane] = vl;
    }
}

// ---------------------------------------------------------------------------
// Persistent whole-rollout kernel: per-row-block flag sync (16 pipelines).
// ---------------------------------------------------------------------------
__global__ __launch_bounds__(256, 2)
void decoder_persistent(const float* __restrict__ bih0, const float* __restrict__ bhh0,
                        const float* __restrict__ bih1, const float* __restrict__ bhh1,
                        const float* __restrict__ Wout, const float* __restrict__ bout,
                        float* __restrict__ out)
{
    extern __shared__ __align__(16) char sm[];
    const int tid = threadIdx.x;
    const int rb  = blockIdx.x & 15;          // row-block of this layer-CTA
    const int hrb = blockIdx.x >> 3;          // row-block of this head-CTA (bid<128)
    unsigned* cA = &g_cA[rb * 8];
    unsigned* cB = &g_cB[rb * 8];
    unsigned* cC = &g_cC[rb * 8];
    unsigned* cBh = &g_cB[(hrb & 15) * 8];
    unsigned* cCh = &g_cC[(hrb & 15) * 8];

    auto arrive = [&](unsigned* c) {
        __threadfence();
        __syncthreads();
        if (tid == 0) atomicAdd(c, 1u);
    };

    for (int s = 0; s < PLEN; s++) {
        const int cur = s & 1;

        // ---- Layer 0: entry = rb's L0(s-1) done; x-tile waits head(s-1) of rb.
        if (tid == 0) spin_until(cA, 16u * (unsigned)s);
        __syncthreads();
        gru_layer_step<0>(sm, cur, bih0, bhh0, cC, 8u * (unsigned)s);
        arrive(cA);

        // ---- Layer 1: entry = rb's L1(s-1); WAR vs head(s-2); x waits L0(s).
        if (tid == 0) {
            spin_until(cB, 16u * (unsigned)s);
            if (s >= 2) spin_until(cC, 8u * (unsigned)(s - 1));
        }
        __syncthreads();
        gru_layer_step<1>(sm, cur, bih1, bhh1, cA, 16u * (unsigned)(s + 1));
        arrive(cB);

        // ---- Head on CTAs 0..127: needs rb=bid>>3's L1(s) done.
        if (blockIdx.x < BATCH / 8) {
            if (tid == 0) spin_until(cBh, 16u * (unsigned)(s + 1));
            __syncthreads();
            head_step(cur, Wout, bout, out, s);
            __threadfence();
            __syncthreads();
            if (tid == 0) atomicAdd(cCh, 1u);
        }
    }

    // final hidden copy
    if (tid < 16) {
        spin_until(&g_cA[tid * 8], 16u * (unsigned)PLEN);
        spin_until(&g_cB[tid * 8], 16u * (unsigned)PLEN);
    }
    __syncthreads();
    constexpr int CH = BATCH * HID / NCTA;   // 2048
    const int base = blockIdx.x * CH;
    float* dst = out + (size_t)BATCH * PLEN * TSZ;
    for (int i = tid; i < CH; i += blockDim.x) {
        dst[base + i]               = __ldcg(&g_h0f[0][base + i]);
        dst[BATCH * HID + base + i] = __ldcg(&g_h1f[0][base + i]);
    }
}

// ---------------------------------------------------------------------------
// init: reset flags, copy/split initial hidden, zero val, convert weights
// ---------------------------------------------------------------------------
__global__ void init_kernel(const float* __restrict__ hidden,
                            const float* __restrict__ Wih0,
                            const float* __restrict__ Whh0,
                            const float* __restrict__ Wih1,
                            const float* __restrict__ Whh1)
{
    const int i = blockIdx.x * blockDim.x + threadIdx.x;
    const __half z16 = __float2half(0.0f);

    if (i < 16 * 8) { g_cA[i] = 0; g_cB[i] = 0; g_cC[i] = 0; }

    if (i < BATCH * HID) {
        const float a = hidden[i];
        const float b = hidden[BATCH * HID + i];
        g_h0f[0][i] = a;
        g_h1f[0][i] = b;
        split_fp16(a, g_h0h[0][i], g_h0l[0][i]);
        split_fp16(b, g_h1h[0][i], g_h1l[0][i]);
    }
    if (i < 2 * BATCH * XP0) {
        (&g_valh[0][0])[i] = z16;
        (&g_vall[0][0])[i] = z16;
    }
    if (i < 3 * HID * XP0) {
        const int r = i / XP0;
        const int k = i % XP0;
        const float ww = (k < TSZ) ? Wih0[r * TSZ + k] : 0.0f;
        g_w0x[i] = __float2half_rn(ww);
    }
    if (i < 3 * HID * HID) {
        g_w0h[i] = __float2half_rn(Whh0[i]);
        g_w1x[i] = __float2half_rn(Wih1[i]);
        g_w1h[i] = __float2half_rn(Whh1[i]);
    }
}

// ---------------------------------------------------------------------------
// host
// ---------------------------------------------------------------------------
extern "C" void kernel_launch(void* const* d_in, const int* in_sizes, int n_in,
                              void* d_out, int out_size)
{
    const float* hidden = (const float*)d_in[0];
    const float* Wih0   = (const float*)d_in[1];
    const float* Whh0   = (const float*)d_in[2];
    const float* bih0   = (const float*)d_in[3];
    const float* bhh0   = (const float*)d_in[4];
    const float* Wih1   = (const float*)d_in[5];
    const float* Whh1   = (const float*)d_in[6];
    const float* bih1   = (const float*)d_in[7];
    const float* bhh1   = (const float*)d_in[8];
    const float* Wout   = (const float*)d_in[9];
    const float* bout   = (const float*)d_in[10];
    float* out = (float*)d_out;

    cudaFuncSetAttribute(decoder_persistent,
                         cudaFuncAttributeMaxDynamicSharedMemorySize, G_SMEM);

    init_kernel<<<(3 * HID * HID + 255) / 256, 256>>>(hidden, Wih0, Whh0, Wih1, Whh1);
    decoder_persistent<<<NCTA, 256, G_SMEM>>>(bih0, bhh0, bih1, bhh1, Wout, bout, out);
}

// round 17
// speedup vs baseline: 2.1199x; 1.2896x over previous
#include <cuda_runtime.h>
#include <cuda_fp16.h>
#include <cstdint>

// Problem constants
#define BATCH 1024
#define HID   512
#define TSZ   24
#define PLEN  256
#define XP0   32          // padded layer0 input width (24 -> 32)
#define NCTA  256         // persistent grid (2 CTAs/SM co-resident)

// GRU layer tile config: CTA-tile = 64 rows x 32 gate-cols, 8 warps
#define TM 64
#define TN 32
#define KT 32             // k per tile
#define AST 40            // smem row stride (fp16 elems): 32 + 8 pad

// dynamic smem layout (bytes): A | W
#define G_APART (64 * AST * 2)            // 5120
#define G_WPART (96 * AST * 2)            // 7680
#define G_STAGE (G_APART + G_WPART)       // 12800
#define G_SMEM  (4*G_STAGE)               // 51200
#define WPLANE  (32 * AST * 2)            // 2560: one plane within W part

// ---------------------------------------------------------------------------
// Device state (no allocation allowed -> __device__ globals)
// ---------------------------------------------------------------------------
__device__ float  g_h0f[2][BATCH * HID];
__device__ float  g_h1f[2][BATCH * HID];
__device__ __half g_h0h[2][BATCH * HID];
__device__ __half g_h1h[2][BATCH * HID];
__device__ __half g_valh[2][BATCH * XP0];
__device__ __half g_w0x[3 * HID * XP0];
__device__ __half g_w0h[3 * HID * HID];
__device__ __half g_w1x[3 * HID * HID];
__device__ __half g_w1h[3 * HID * HID];
// per-row-block arrival counters, padded to separate 32B sectors
__device__ unsigned g_cA[16 * 8], g_cB[16 * 8], g_cC[16 * 8];

// ---------------------------------------------------------------------------
// helpers
// ---------------------------------------------------------------------------
__device__ __forceinline__ float sigf(float x) { return 1.0f / (1.0f + __expf(-x)); }
__device__ __forceinline__ float tanhf_fast(float x) {
    return 1.0f - 2.0f / (__expf(2.0f * x) + 1.0f);
}

__device__ __forceinline__ uint32_t smem_u32(const void* p) {
    uint32_t a;
    asm("{ .reg .u64 t; cvta.to.shared.u64 t, %1; cvt.u32.u64 %0, t; }" : "=r"(a) : "l"(p));
    return a;
}

__device__ __forceinline__ void cpa16(uint32_t dst, const void* src) {
    asm volatile("cp.async.cg.shared.global [%0], [%1], 16;" :: "r"(dst), "l"(src) : "memory");
}
__device__ __forceinline__ void cpa_commit() {
    asm volatile("cp.async.commit_group;" ::: "memory");
}
template<int N>
__device__ __forceinline__ void cpa_wait() {
    asm volatile("cp.async.wait_group %0;" :: "n"(N) : "memory");
}

__device__ __forceinline__ void ldsm4(uint32_t* r, uint32_t addr) {
    asm volatile("ldmatrix.sync.aligned.m8n8.x4.shared.b16 {%0,%1,%2,%3}, [%4];"
                 : "=r"(r[0]), "=r"(r[1]), "=r"(r[2]), "=r"(r[3]) : "r"(addr));
}

__device__ __forceinline__ void mma_fp16(float* c, const uint32_t* a,
                                         uint32_t b0, uint32_t b1) {
    asm volatile(
        "mma.sync.aligned.m16n8k16.row.col.f32.f16.f16.f32 "
        "{%0,%1,%2,%3}, {%4,%5,%6,%7}, {%8,%9}, {%0,%1,%2,%3};"
        : "+f"(c[0]), "+f"(c[1]), "+f"(c[2]), "+f"(c[3])
        : "r"(a[0]), "r"(a[1]), "r"(a[2]), "r"(a[3]), "r"(b0), "r"(b1));
}

__device__ __forceinline__ unsigned ld_acq(const unsigned* p) {
    unsigned v;
    asm volatile("ld.acquire.gpu.global.u32 %0, [%1];" : "=r"(v) : "l"(p));
    return v;
}
__device__ __forceinline__ void spin_until(const unsigned* c, unsigned tgt) {
    unsigned v = ld_acq(c);
    while (v < tgt) { __nanosleep(32); v = ld_acq(c); }
}

// ---------------------------------------------------------------------------
// GRU layer step: CTA = 64 rows x 32 cols; warp = 16 rows x 16 cols.
// Plain fp16 GEMM (A and W fp16-rounded; fp32 accumulate).
// Tile order: h-phase tiles FIRST, x-phase tiles LAST (x staging waits xcnt).
// ---------------------------------------------------------------------------
template<int LAYER>
__device__ __forceinline__ void gru_layer_step(char* sm, int cur,
                                               const float* __restrict__ bih,
                                               const float* __restrict__ bhh,
                                               const unsigned* xcnt, unsigned xtgt)
{
    constexpr int KPH0 = (LAYER == 0) ? XP0 : HID;  // x-phase K
    constexpr int NTH  = HID / KT;                  // 16 h-tiles
    constexpr int NT   = NTH + KPH0 / KT;           // 17 or 32
    const int nxt = cur ^ 1;

    const __half* __restrict__ xh = (LAYER == 0) ? g_valh[cur] : g_h0h[nxt];
    const __half* __restrict__ hh = (LAYER == 0) ? g_h0h[cur] : g_h1h[cur];
    const float* __restrict__ hinf = (LAYER == 0) ? g_h0f[cur] : g_h1f[cur];
    float* __restrict__ houtf      = (LAYER == 0) ? g_h0f[nxt] : g_h1f[nxt];
    __half* __restrict__ houth     = (LAYER == 0) ? g_h0h[nxt] : g_h1h[nxt];
    const __half* __restrict__ Wx  = (LAYER == 0) ? g_w0x : g_w1x;
    const __half* __restrict__ Wh  = (LAYER == 0) ? g_w0h : g_w1h;

    const int tid  = threadIdx.x;
    const int w    = tid >> 5;
    const int l    = tid & 31;
    const int rg   = w & 3;
    const int ch   = w >> 2;
    const int rowBase = (blockIdx.x & 15) * TM;
    const int colBase = (blockIdx.x >> 4) * TN;
    const uint32_t smb = smem_u32(sm);

    // accumulators: [plane r,z,inn,hn][nf(2)][reg(4)] = 32 regs
    float cAcc[4][2][4];
    {
        const int c4 = l & 3;
        #pragma unroll
        for (int nf = 0; nf < 2; nf++) {
            const int j0 = colBase + ch * 16 + nf * 8 + 2 * c4;
            const float br0 = __ldg(bih + j0)     + __ldg(bhh + j0);
            const float br1 = __ldg(bih + j0 + 1) + __ldg(bhh + j0 + 1);
            const float bz0 = __ldg(bih + HID + j0)     + __ldg(bhh + HID + j0);
            const float bz1 = __ldg(bih + HID + j0 + 1) + __ldg(bhh + HID + j0 + 1);
            const float bi0 = __ldg(bih + 2 * HID + j0);
            const float bi1 = __ldg(bih + 2 * HID + j0 + 1);
            const float bn0 = __ldg(bhh + 2 * HID + j0);
            const float bn1 = __ldg(bhh + 2 * HID + j0 + 1);
            cAcc[0][nf][0] = br0; cAcc[0][nf][1] = br1; cAcc[0][nf][2] = br0; cAcc[0][nf][3] = br1;
            cAcc[1][nf][0] = bz0; cAcc[1][nf][1] = bz1; cAcc[1][nf][2] = bz0; cAcc[1][nf][3] = bz1;
            cAcc[2][nf][0] = bi0; cAcc[2][nf][1] = bi1; cAcc[2][nf][2] = bi0; cAcc[2][nf][3] = bi1;
            cAcc[3][nf][0] = bn0; cAcc[3][nf][1] = bn1; cAcc[3][nf][2] = bn0; cAcc[3][nf][3] = bn1;
        }
    }

    // ---- A loader: 256 (row,kc) chunks over 256 threads ----
    const int aRow   = rowBase + (tid >> 2);
    const int akcOff = (tid & 3) << 3;
    const uint32_t aDst = (uint32_t)(((tid >> 2) * AST + ((tid & 3) << 3)) << 1);
    const __half* aBaseH = hh + (size_t)aRow * HID  + akcOff;
    const __half* aBaseX = xh + (size_t)aRow * KPH0 + akcOff;

    // ---- W loader: 384 chunks; chunk1 = tid, chunk2 = tid+256 (tid<128) ----
    const int rr1 = tid >> 2;                    // rows 0..63 (planes 0..1)
    const int cc1 = (tid & 3) << 3;
    const int gr1 = (rr1 >> 5) * HID + colBase + (rr1 & 31);
    const uint32_t wDst1 = (uint32_t)(G_APART + ((rr1 * AST + cc1) << 1));
    const __half* w1H = Wh + (size_t)gr1 * HID  + cc1;
    const __half* w1X = Wx + (size_t)gr1 * KPH0 + cc1;

    const int rr2 = 64 + (tid >> 2);             // rows 64..95 (plane 2), tid<128
    const int cc2 = (tid & 3) << 3;
    const int gr2 = 2 * HID + colBase + (rr2 & 31);
    const uint32_t wDst2 = (uint32_t)(G_APART + ((rr2 * AST + cc2) << 1));
    const __half* w2H = Wh + (size_t)gr2 * HID  + cc2;
    const __half* w2X = Wx + (size_t)gr2 * KPH0 + cc2;

    // ---- ldmatrix byte offsets ----
    const uint32_t aOffB =
        (uint32_t)(((rg * 16 + (l & 7) + (((l >> 3) & 1) << 3)) * AST + ((l >> 4) << 3)) << 1);
    const uint32_t wOffB =
        (uint32_t)(((ch * 16 + (l & 7) + (((l >> 4) & 1) << 3)) * AST + (((l >> 3) & 1) << 3)) << 1);

    auto stageT = [&](int t) {
        const int buf = t & 3;
        const bool hph = (t < NTH);
        const int koff = (hph ? t : t - NTH) * KT;
        const uint32_t stg = smb + buf * G_STAGE;
        cpa16(stg + aDst,  (hph ? aBaseH : aBaseX) + koff);
        cpa16(stg + wDst1, (hph ? w1H : w1X) + koff);
        if (tid < 128) cpa16(stg + wDst2, (hph ? w2H : w2X) + koff);
    };

    auto computeT = [&](int t) {
        const int buf = t & 3;
        const bool hph = (t < NTH);
        const uint32_t stg = smb + buf * G_STAGE;
        const uint32_t aHp = stg + aOffB;
        const uint32_t wHp = stg + G_APART + wOffB;
        #pragma unroll
        for (int kc = 0; kc < 2; kc++) {
            uint32_t ah[4];
            ldsm4(ah, aHp + kc * 32);
            #pragma unroll
            for (int p = 0; p < 3; p++) {
                uint32_t bh[4];
                ldsm4(bh, wHp + p * WPLANE + kc * 32);
                float (*C)[4] = (p == 2) ? (hph ? cAcc[3] : cAcc[2]) : cAcc[p];
                #pragma unroll
                for (int nf = 0; nf < 2; nf++)
                    mma_fp16(C[nf], ah, bh[2 * nf], bh[2 * nf + 1]);
            }
        }
    };

    stageT(0); cpa_commit();
    stageT(1); cpa_commit();
    stageT(2); cpa_commit();
    for (int t = 0; t < NT; t++) {
        cpa_wait<2>();
        if (t + 3 == NTH && tid == 0) spin_until(xcnt, xtgt);
        __syncthreads();
        computeT(t);
        if (t + 3 < NT) stageT(t + 3);
        cpa_commit();
    }

    // GRU epilogue (hinf via __ldcg: L2-coherent cross-CTA reads)
    const int g  = l >> 2;
    const int c4 = l & 3;
    const int R0 = rowBase + rg * 16 + g;
    const int R1 = R0 + 8;
    #pragma unroll
    for (int nf = 0; nf < 2; nf++) {
        const int j0 = colBase + ch * 16 + nf * 8 + 2 * c4;
        const float2 h0v = __ldcg((const float2*)(hinf + (size_t)R0 * HID + j0));
        const float2 h1v = __ldcg((const float2*)(hinf + (size_t)R1 * HID + j0));
        float o[4];
        const float hvv[4] = { h0v.x, h0v.y, h1v.x, h1v.y };
        #pragma unroll
        for (int i = 0; i < 4; i++) {
            const float r_ = sigf(cAcc[0][nf][i]);
            const float z_ = sigf(cAcc[1][nf][i]);
            const float n_ = tanhf_fast(cAcc[2][nf][i] + r_ * cAcc[3][nf][i]);
            o[i] = (1.0f - z_) * n_ + z_ * hvv[i];
        }
        *(float2*)&houtf[(size_t)R0 * HID + j0] = make_float2(o[0], o[1]);
        *(float2*)&houtf[(size_t)R1 * HID + j0] = make_float2(o[2], o[3]);
        *(__half2*)&houth[(size_t)R0 * HID + j0] =
            __halves2half2(__float2half_rn(o[0]), __float2half_rn(o[1]));
        *(__half2*)&houth[(size_t)R1 * HID + j0] =
            __halves2half2(__float2half_rn(o[2]), __float2half_rn(o[3]));
    }
}

// ---------------------------------------------------------------------------
// Output head: warp-per-row on CTAs 0..127 (1024 rows).
// ---------------------------------------------------------------------------
__device__ __forceinline__ void head_step(int cur,
                                          const float* __restrict__ Wout,
                                          const float* __restrict__ bout,
                                          float* __restrict__ outputs, int step)
{
    const int nxt  = cur ^ 1;
    const int w    = threadIdx.x >> 5;
    const int lane = threadIdx.x & 31;
    const int row  = blockIdx.x * 8 + w;
    const float* __restrict__ h1 = g_h1f[nxt];

    float xv[16];
    {
        const float4* hr = (const float4*)(h1 + (size_t)row * HID);
        #pragma unroll
        for (int q = 0; q < 4; q++) {
            float4 v = __ldcg(&hr[lane * 4 + q]);
            xv[q * 4 + 0] = fmaxf(v.x, 0.f);
            xv[q * 4 + 1] = fmaxf(v.y, 0.f);
            xv[q * 4 + 2] = fmaxf(v.z, 0.f);
            xv[q * 4 + 3] = fmaxf(v.w, 0.f);
        }
    }

    float s[TSZ];
    #pragma unroll
    for (int j = 0; j < TSZ; j++) {
        const float4* wr = (const float4*)(Wout + (size_t)j * HID + lane * 16);
        float a = 0.f;
        #pragma unroll
        for (int q = 0; q < 4; q++) {
            const float4 wv = __ldg(&wr[q]);
            a = fmaf(xv[q * 4 + 0], wv.x, a);
            a = fmaf(xv[q * 4 + 1], wv.y, a);
            a = fmaf(xv[q * 4 + 2], wv.z, a);
            a = fmaf(xv[q * 4 + 3], wv.w, a);
        }
        s[j] = a;
    }

    #pragma unroll
    for (int off = 16; off >= 1; off >>= 1) {
        #pragma unroll
        for (int j = 0; j < TSZ; j++)
            s[j] += __shfl_xor_sync(0xFFFFFFFFu, s[j], off);
    }

    if (lane < TSZ) {
        const float v = sigf(s[lane] + __ldg(bout + lane));
        outputs[(size_t)row * (PLEN * TSZ) + (size_t)step * TSZ + lane] = v;
        g_valh[nxt][row * XP0 + lane] = __float2half_rn(v);
    }
}

// ---------------------------------------------------------------------------
// Persistent whole-rollout kernel: per-row-block flag sync (16 pipelines).
// ---------------------------------------------------------------------------
__global__ __launch_bounds__(256, 2)
void decoder_persistent(const float* __restrict__ bih0, const float* __restrict__ bhh0,
                        const float* __restrict__ bih1, const float* __restrict__ bhh1,
                        const float* __restrict__ Wout, const float* __restrict__ bout,
                        float* __restrict__ out)
{
    extern __shared__ __align__(16) char sm[];
    const int tid = threadIdx.x;
    const int rb  = blockIdx.x & 15;          // row-block of this layer-CTA
    const int hrb = blockIdx.x >> 3;          // row-block of this head-CTA (bid<128)
    unsigned* cA = &g_cA[rb * 8];
    unsigned* cB = &g_cB[rb * 8];
    unsigned* cC = &g_cC[rb * 8];
    unsigned* cBh = &g_cB[(hrb & 15) * 8];
    unsigned* cCh = &g_cC[(hrb & 15) * 8];

    auto arrive = [&](unsigned* c) {
        __threadfence();
        __syncthreads();
        if (tid == 0) atomicAdd(c, 1u);
    };

    for (int s = 0; s < PLEN; s++) {
        const int cur = s & 1;

        // ---- Layer 0: entry = rb's L0(s-1) done; x-tile waits head(s-1) of rb.
        if (tid == 0) spin_until(cA, 16u * (unsigned)s);
        __syncthreads();
        gru_layer_step<0>(sm, cur, bih0, bhh0, cC, 8u * (unsigned)s);
        arrive(cA);

        // ---- Layer 1: entry = rb's L1(s-1); WAR vs head(s-2); x waits L0(s).
        if (tid == 0) {
            spin_until(cB, 16u * (unsigned)s);
            if (s >= 2) spin_until(cC, 8u * (unsigned)(s - 1));
        }
        __syncthreads();
        gru_layer_step<1>(sm, cur, bih1, bhh1, cA, 16u * (unsigned)(s + 1));
        arrive(cB);

        // ---- Head on CTAs 0..127: needs rb=bid>>3's L1(s) done.
        if (blockIdx.x < BATCH / 8) {
            if (tid == 0) spin_until(cBh, 16u * (unsigned)(s + 1));
            __syncthreads();
            head_step(cur, Wout, bout, out, s);
            __threadfence();
            __syncthreads();
            if (tid == 0) atomicAdd(cCh, 1u);
        }
    }

    // final hidden copy
    if (tid < 16) {
        spin_until(&g_cA[tid * 8], 16u * (unsigned)PLEN);
        spin_until(&g_cB[tid * 8], 16u * (unsigned)PLEN);
    }
    __syncthreads();
    constexpr int CH = BATCH * HID / NCTA;   // 2048
    const int base = blockIdx.x * CH;
    float* dst = out + (size_t)BATCH * PLEN * TSZ;
    for (int i = tid; i < CH; i += blockDim.x) {
        dst[base + i]               = __ldcg(&g_h0f[0][base + i]);
        dst[BATCH * HID + base + i] = __ldcg(&g_h1f[0][base + i]);
    }
}

// ---------------------------------------------------------------------------
// init: reset flags, copy/convert initial hidden, zero val, convert weights
// ---------------------------------------------------------------------------
__global__ void init_kernel(const float* __restrict__ hidden,
                            const float* __restrict__ Wih0,
                            const float* __restrict__ Whh0,
                            const float* __restrict__ Wih1,
                            const float* __restrict__ Whh1)
{
    const int i = blockIdx.x * blockDim.x + threadIdx.x;
    const __half z16 = __float2half(0.0f);

    if (i < 16 * 8) { g_cA[i] = 0; g_cB[i] = 0; g_cC[i] = 0; }

    if (i < BATCH * HID) {
        const float a = hidden[i];
        const float b = hidden[BATCH * HID + i];
        g_h0f[0][i] = a;
        g_h1f[0][i] = b;
        g_h0h[0][i] = __float2half_rn(a);
        g_h1h[0][i] = __float2half_rn(b);
    }
    if (i < 2 * BATCH * XP0) {
        (&g_valh[0][0])[i] = z16;
    }
    if (i < 3 * HID * XP0) {
        const int r = i / XP0;
        const int k = i % XP0;
        const float ww = (k < TSZ) ? Wih0[r * TSZ + k] : 0.0f;
        g_w0x[i] = __float2half_rn(ww);
    }
    if (i < 3 * HID * HID) {
        g_w0h[i] = __float2half_rn(Whh0[i]);
        g_w1x[i] = __float2half_rn(Wih1[i]);
        g_w1h[i] = __float2half_rn(Whh1[i]);
    }
}

// ---------------------------------------------------------------------------
// host
// ---------------------------------------------------------------------------
extern "C" void kernel_launch(void* const* d_in, const int* in_sizes, int n_in,
                              void* d_out, int out_size)
{
    const float* hidden = (const float*)d_in[0];
    const float* Wih0   = (const float*)d_in[1];
    const float* Whh0   = (const float*)d_in[2];
    const float* bih0   = (const float*)d_in[3];
    const float* bhh0   = (const float*)d_in[4];
    const float* Wih1   = (const float*)d_in[5];
    const float* Whh1   = (const float*)d_in[6];
    const float* bih1   = (const float*)d_in[7];
    const float* bhh1   = (const float*)d_in[8];
    const float* Wout   = (const float*)d_in[9];
    const float* bout   = (const float*)d_in[10];
    float* out = (float*)d_out;

    cudaFuncSetAttribute(decoder_persistent,
                         cudaFuncAttributeMaxDynamicSharedMemorySize, G_SMEM);

    init_kernel<<<(3 * HID * HID + 255) / 256, 256>>>(hidden, Wih0, Whh0, Wih1, Whh1);
    decoder_persistent<<<NCTA, 256, G_SMEM>>>(bih0, bhh0, bih1, bhh1, Wout, bout, out);
}